// round 3
// baseline (speedup 1.0000x reference)
// R2: bf16-split tensor-core GEMMs (mma.sync m16n8k16 + ldmatrix) + fp32 flash attention.
// Label: "mma-bf16-split3".
#include <cuda_runtime.h>
#include <cuda_bf16.h>
#include <cstdint>

// Problem constants (Qwen2 GQA): B=2, S=2048, D=3584, H=28, KV=4, HD=128
#define Bn    2
#define Sn    2048
#define Dn    3584
#define Hn    28
#define KVn   4
#define HDn   128
#define NREP  7
#define Mn    (Bn * Sn)          // 4096 rows
#define KVD   (KVn * HDn)        // 512
#define K3n   (3 * Dn)           // 10752 (split-expanded K)
#define SCALE 0.08838834764831845f

// fp32 scratch
__device__ float g_q[(size_t)Mn * Dn];
__device__ float g_k[(size_t)Mn * KVD];
__device__ float g_v[(size_t)Mn * KVD];
__device__ float g_attn[(size_t)Mn * Dn];
// bf16 split-expanded operands
__device__ __nv_bfloat16 g_a3 [(size_t)Mn  * K3n];   // x3, later attn3 (reused)
__device__ __nv_bfloat16 g_wq3[(size_t)Dn  * K3n];
__device__ __nv_bfloat16 g_wk3[(size_t)KVD * K3n];
__device__ __nv_bfloat16 g_wv3[(size_t)KVD * K3n];
__device__ __nv_bfloat16 g_wo3[(size_t)Dn  * K3n];

// ---------------------------------------------------------------------------
// Split-expand: fp32 [R,K] -> bf16 [R,3K].
// a_mode=1 (activations): triplet (hi, hi, lo); a_mode=0 (weights): (hi, lo, hi).
// Dot over 3K yields hiA*hiW + hiA*loW + loA*hiW  (error ~2^-18).
// ---------------------------------------------------------------------------
__global__ void expand3_kernel(const float* __restrict__ in,
                               __nv_bfloat16* __restrict__ out,
                               int total, int a_mode)
{
    int idx = blockIdx.x * blockDim.x + threadIdx.x;
    if (idx >= total) return;
    float v = in[idx];
    __nv_bfloat16 hi = __float2bfloat16(v);
    __nv_bfloat16 lo = __float2bfloat16(v - __bfloat162float(hi));
    size_t o = (size_t)idx * 3;
    if (a_mode) { out[o] = hi; out[o + 1] = hi; out[o + 2] = lo; }
    else        { out[o] = hi; out[o + 1] = lo; out[o + 2] = hi; }
}

// ---------------------------------------------------------------------------
// bf16 tensor-core GEMM: C[M,N] = A[M,K]*W[N,K]^T (+bias), fp32 accum/out.
// 128x128 block tile, BK=32, 256 threads = 8 warps (4 along M x 2 along N),
// warp tile 32x64. mma.sync.m16n8k16 row.col, operands via ldmatrix.
// smem rows padded to 40 bf16 (80B) for conflict-free LDSM.
// ---------------------------------------------------------------------------
#define LDA 40

__device__ __forceinline__ void ldsm4(uint32_t& r0, uint32_t& r1,
                                      uint32_t& r2, uint32_t& r3, uint32_t addr)
{
    asm volatile("ldmatrix.sync.aligned.m8n8.x4.shared.b16 {%0,%1,%2,%3}, [%4];\n"
                 : "=r"(r0), "=r"(r1), "=r"(r2), "=r"(r3) : "r"(addr));
}

__device__ __forceinline__ void mma16816(float* c, const uint32_t* a,
                                         uint32_t b0, uint32_t b1)
{
    asm volatile(
        "mma.sync.aligned.m16n8k16.row.col.f32.bf16.bf16.f32 "
        "{%0,%1,%2,%3}, {%4,%5,%6,%7}, {%8,%9}, {%0,%1,%2,%3};\n"
        : "+f"(c[0]), "+f"(c[1]), "+f"(c[2]), "+f"(c[3])
        : "r"(a[0]), "r"(a[1]), "r"(a[2]), "r"(a[3]), "r"(b0), "r"(b1));
}

__global__ void __launch_bounds__(256) gemm_bf16_kernel(
    const __nv_bfloat16* __restrict__ A, const __nv_bfloat16* __restrict__ W,
    const float* __restrict__ bias, float* __restrict__ C, int N, int K)
{
    __shared__ __nv_bfloat16 As[128 * LDA];
    __shared__ __nv_bfloat16 Ws[128 * LDA];

    const int tid  = threadIdx.x;
    const int lane = tid & 31, wid = tid >> 5;
    const int m0 = blockIdx.y << 7, n0 = blockIdx.x << 7;
    const int wm = (wid & 3) << 5;        // warp M offset: 0/32/64/96
    const int wn = (wid >> 2) << 6;       // warp N offset: 0/64

    // global->smem: each thread one int4 (8 bf16) per 64-row half
    const int lr = tid >> 2;              // 0..63
    const int ls = (tid & 3) << 3;        // 0/8/16/24
    const __nv_bfloat16* Ag = A + (size_t)(m0 + lr) * K + ls;
    const __nv_bfloat16* Wg = W + (size_t)(n0 + lr) * K + ls;

    // ldmatrix lane->address components
    const int a_row  = wm + (lane & 15);
    const int a_coff = (lane >> 4) << 3;
    const int b_row  = wn + ((lane >> 4) << 3) + (lane & 7);
    const int b_coff = ((lane >> 3) & 1) << 3;

    const uint32_t as_base = (uint32_t)__cvta_generic_to_shared(As);
    const uint32_t ws_base = (uint32_t)__cvta_generic_to_shared(Ws);

    float acc[2][8][4];
#pragma unroll
    for (int i = 0; i < 2; ++i)
#pragma unroll
        for (int j = 0; j < 8; ++j)
#pragma unroll
            for (int e = 0; e < 4; ++e) acc[i][j][e] = 0.f;

    for (int k0 = 0; k0 < K; k0 += 32) {
        __syncthreads();
        *(int4*)(&As[lr * LDA + ls])        = *(const int4*)(Ag + k0);
        *(int4*)(&As[(lr + 64) * LDA + ls]) = *(const int4*)(Ag + (size_t)64 * K + k0);
        *(int4*)(&Ws[lr * LDA + ls])        = *(const int4*)(Wg + k0);
        *(int4*)(&Ws[(lr + 64) * LDA + ls]) = *(const int4*)(Wg + (size_t)64 * K + k0);
        __syncthreads();

#pragma unroll
        for (int kk = 0; kk < 32; kk += 16) {
            uint32_t afr[2][4];
#pragma unroll
            for (int mi = 0; mi < 2; ++mi) {
                uint32_t addr = as_base +
                    (uint32_t)(((a_row + mi * 16) * LDA + kk + a_coff) * 2);
                ldsm4(afr[mi][0], afr[mi][1], afr[mi][2], afr[mi][3], addr);
            }
            uint32_t bfr[4][4];   // per nq: {t0.b0, t0.b1, t1.b0, t1.b1}
#pragma unroll
            for (int nq = 0; nq < 4; ++nq) {
                uint32_t addr = ws_base +
                    (uint32_t)(((b_row + nq * 16) * LDA + kk + b_coff) * 2);
                ldsm4(bfr[nq][0], bfr[nq][1], bfr[nq][2], bfr[nq][3], addr);
            }
#pragma unroll
            for (int mi = 0; mi < 2; ++mi)
#pragma unroll
                for (int nq = 0; nq < 4; ++nq) {
                    mma16816(acc[mi][nq * 2 + 0], afr[mi], bfr[nq][0], bfr[nq][1]);
                    mma16816(acc[mi][nq * 2 + 1], afr[mi], bfr[nq][2], bfr[nq][3]);
                }
        }
    }

    // Epilogue: c0,c1 at (g, t*2|+1), c2,c3 at (g+8, ...)
    const int g = lane >> 2, t = lane & 3;
#pragma unroll
    for (int mi = 0; mi < 2; ++mi)
#pragma unroll
        for (int ni = 0; ni < 8; ++ni) {
            int row = m0 + wm + mi * 16 + g;
            int col = n0 + wn + ni * 8 + t * 2;
            float b0 = bias ? bias[col]     : 0.f;
            float b1 = bias ? bias[col + 1] : 0.f;
            C[(size_t)row * N + col]           = acc[mi][ni][0] + b0;
            C[(size_t)row * N + col + 1]       = acc[mi][ni][1] + b1;
            C[(size_t)(row + 8) * N + col]     = acc[mi][ni][2] + b0;
            C[(size_t)(row + 8) * N + col + 1] = acc[mi][ni][3] + b1;
        }
}

// ---------------------------------------------------------------------------
// RoPE, in place on g_q / g_k (unchanged from baseline).
// ---------------------------------------------------------------------------
__global__ void rope_kernel(const float* __restrict__ cosT,
                            const float* __restrict__ sinT)
{
    const int QP = Mn * Hn * 64;
    const int TP = QP + Mn * KVn * 64;
    int idx = blockIdx.x * blockDim.x + threadIdx.x;
    if (idx >= TP) return;

    float* ptr;
    int s, p;
    if (idx < QP) {
        p = idx & 63;
        int hh = (idx >> 6) % Hn;
        int bs = idx / (64 * Hn);
        s = bs & (Sn - 1);
        ptr = g_q + (size_t)bs * Dn + hh * HDn + 2 * p;
    } else {
        int t = idx - QP;
        p = t & 63;
        int kv = (t >> 6) & 3;
        int bs = t >> 8;
        s = bs & (Sn - 1);
        ptr = g_k + (size_t)bs * KVD + kv * HDn + 2 * p;
    }
    float c  = cosT[s * 64 + p];
    float sn = sinT[s * 64 + p];
    float xr = ptr[0], xi = ptr[1];
    ptr[0] = xr * c - xi * sn;
    ptr[1] = xr * sn + xi * c;
}

// ---------------------------------------------------------------------------
// fp32 flash attention, causal, GQA (unchanged from baseline).
// ---------------------------------------------------------------------------
#define LQ 132
#define LP 68
#define ATTN_SMEM ((64 * LQ * 2 + 64 * 128 + 64 * LP) * 4)   // 117760 bytes

__global__ void __launch_bounds__(256) attn_kernel()
{
    extern __shared__ float sm[];
    float* Qs = sm;
    float* Ks = Qs + 64 * LQ;
    float* Vs = Ks + 64 * LQ;
    float* Ps = Vs + 64 * 128;

    const int qt = blockIdx.x, h = blockIdx.y, b = blockIdx.z;
    const int kvh = h / NREP;
    const int tid = threadIdx.x;
    const int tx = tid & 15, ty = tid >> 4;
    const int qi0 = qt << 6;

    const float* qbase = g_q + (size_t)(b * Sn + qi0) * Dn + h * HDn;
    for (int i = tid; i < 64 * 32; i += 256) {
        int r = i >> 5, c4 = (i & 31) << 2;
        *(float4*)(Qs + r * LQ + c4) = *(const float4*)(qbase + (size_t)r * Dn + c4);
    }

    float m[4], l[4], o[4][8];
#pragma unroll
    for (int i = 0; i < 4; ++i) {
        m[i] = -1e30f; l[i] = 0.f;
#pragma unroll
        for (int d = 0; d < 8; ++d) o[i][d] = 0.f;
    }

    const float* kb_g = g_k + (size_t)(b * Sn) * KVD + kvh * HDn;
    const float* vb_g = g_v + (size_t)(b * Sn) * KVD + kvh * HDn;

    for (int j0 = 0; j0 <= qi0; j0 += 64) {
        __syncthreads();
        for (int i = tid; i < 64 * 32; i += 256) {
            int r = i >> 5, c4 = (i & 31) << 2;
            *(float4*)(Ks + r * LQ  + c4) = *(const float4*)(kb_g + (size_t)(j0 + r) * KVD + c4);
            *(float4*)(Vs + r * 128 + c4) = *(const float4*)(vb_g + (size_t)(j0 + r) * KVD + c4);
        }
        __syncthreads();

        float sacc[4][4];
#pragma unroll
        for (int i = 0; i < 4; ++i)
#pragma unroll
            for (int j = 0; j < 4; ++j) sacc[i][j] = 0.f;

        for (int k = 0; k < 128; k += 4) {
            float4 qa[4], kb[4];
#pragma unroll
            for (int i = 0; i < 4; ++i)
                qa[i] = *(const float4*)(Qs + (ty * 4 + i) * LQ + k);
#pragma unroll
            for (int j = 0; j < 4; ++j)
                kb[j] = *(const float4*)(Ks + (tx * 4 + j) * LQ + k);
#pragma unroll
            for (int i = 0; i < 4; ++i)
#pragma unroll
                for (int j = 0; j < 4; ++j)
                    sacc[i][j] += qa[i].x * kb[j].x + qa[i].y * kb[j].y
                                + qa[i].z * kb[j].z + qa[i].w * kb[j].w;
        }

        const bool diag = (j0 == qi0);
#pragma unroll
        for (int i = 0; i < 4; ++i)
#pragma unroll
            for (int j = 0; j < 4; ++j) {
                float s = sacc[i][j] * SCALE;
                if (diag && (tx * 4 + j > ty * 4 + i)) s = -1e30f;
                sacc[i][j] = s;
            }

#pragma unroll
        for (int i = 0; i < 4; ++i) {
            float rm = sacc[i][0];
#pragma unroll
            for (int j = 1; j < 4; ++j) rm = fmaxf(rm, sacc[i][j]);
#pragma unroll
            for (int off = 8; off > 0; off >>= 1)
                rm = fmaxf(rm, __shfl_xor_sync(0xffffffffu, rm, off));
            float mn = fmaxf(m[i], rm);
            float alpha = __expf(m[i] - mn);
            float rs = 0.f;
#pragma unroll
            for (int j = 0; j < 4; ++j) {
                float p = __expf(sacc[i][j] - mn);
                sacc[i][j] = p;
                rs += p;
            }
#pragma unroll
            for (int off = 8; off > 0; off >>= 1)
                rs += __shfl_xor_sync(0xffffffffu, rs, off);
            l[i] = l[i] * alpha + rs;
            m[i] = mn;
#pragma unroll
            for (int d = 0; d < 8; ++d) o[i][d] *= alpha;
#pragma unroll
            for (int j = 0; j < 4; ++j)
                Ps[(ty * 4 + i) * LP + tx * 4 + j] = sacc[i][j];
        }
        __syncthreads();

        for (int j = 0; j < 64; ++j) {
            float4 v0 = *(const float4*)(Vs + j * 128 + tx * 8);
            float4 v1 = *(const float4*)(Vs + j * 128 + tx * 8 + 4);
#pragma unroll
            for (int i = 0; i < 4; ++i) {
                float p = Ps[(ty * 4 + i) * LP + j];
                o[i][0] += p * v0.x; o[i][1] += p * v0.y;
                o[i][2] += p * v0.z; o[i][3] += p * v0.w;
                o[i][4] += p * v1.x; o[i][5] += p * v1.y;
                o[i][6] += p * v1.z; o[i][7] += p * v1.w;
            }
        }
    }

    float* ob = g_attn + (size_t)(b * Sn + qi0) * Dn + h * HDn + tx * 8;
#pragma unroll
    for (int i = 0; i < 4; ++i) {
        float inv = 1.f / l[i];
        float outv[8];
#pragma unroll
        for (int d = 0; d < 8; ++d) outv[d] = o[i][d] * inv;
        float* p = ob + (size_t)(ty * 4 + i) * Dn;
        *(float4*)(p)     = *(float4*)(outv);
        *(float4*)(p + 4) = *(float4*)(outv + 4);
    }
}

// ---------------------------------------------------------------------------
// Launch. Inputs: x, wq_w, wq_b, wk_w, wk_b, wv_w, wv_b, wo_w, k_cache,
// v_cache, freqs_cos, freqs_sin, mask, start_pos. start_pos==0 -> caches/mask unused.
// ---------------------------------------------------------------------------
extern "C" void kernel_launch(void* const* d_in, const int* in_sizes, int n_in,
                              void* d_out, int out_size)
{
    const float* x    = (const float*)d_in[0];
    const float* wq_w = (const float*)d_in[1];
    const float* wq_b = (const float*)d_in[2];
    const float* wk_w = (const float*)d_in[3];
    const float* wk_b = (const float*)d_in[4];
    const float* wv_w = (const float*)d_in[5];
    const float* wv_b = (const float*)d_in[6];
    const float* wo_w = (const float*)d_in[7];
    const float* fcos = (const float*)d_in[10];
    const float* fsin = (const float*)d_in[11];
    float* out = (float*)d_out;

    float *q_p, *k_p, *v_p, *attn_p;
    __nv_bfloat16 *a3, *wq3, *wk3, *wv3, *wo3;
    cudaGetSymbolAddress((void**)&q_p,    g_q);
    cudaGetSymbolAddress((void**)&k_p,    g_k);
    cudaGetSymbolAddress((void**)&v_p,    g_v);
    cudaGetSymbolAddress((void**)&attn_p, g_attn);
    cudaGetSymbolAddress((void**)&a3,  g_a3);
    cudaGetSymbolAddress((void**)&wq3, g_wq3);
    cudaGetSymbolAddress((void**)&wk3, g_wk3);
    cudaGetSymbolAddress((void**)&wv3, g_wv3);
    cudaGetSymbolAddress((void**)&wo3, g_wo3);

    const int TPB = 256;
    auto cdiv = [](int a, int b) { return (a + b - 1) / b; };

    // Split-expand activations and weights to bf16 triplets
    expand3_kernel<<<cdiv(Mn * Dn,  TPB), TPB>>>(x,    a3,  Mn * Dn,  1);
    expand3_kernel<<<cdiv(Dn * Dn,  TPB), TPB>>>(wq_w, wq3, Dn * Dn,  0);
    expand3_kernel<<<cdiv(KVD * Dn, TPB), TPB>>>(wk_w, wk3, KVD * Dn, 0);
    expand3_kernel<<<cdiv(KVD * Dn, TPB), TPB>>>(wv_w, wv3, KVD * Dn, 0);
    expand3_kernel<<<cdiv(Dn * Dn,  TPB), TPB>>>(wo_w, wo3, Dn * Dn,  0);

    // QKV projections (tensor cores)
    gemm_bf16_kernel<<<dim3(Dn / 128,  Mn / 128), TPB>>>(a3, wq3, wq_b, q_p, Dn,  K3n);
    gemm_bf16_kernel<<<dim3(KVD / 128, Mn / 128), TPB>>>(a3, wk3, wk_b, k_p, KVD, K3n);
    gemm_bf16_kernel<<<dim3(KVD / 128, Mn / 128), TPB>>>(a3, wv3, wv_b, v_p, KVD, K3n);

    // RoPE
    int nrope = Mn * Hn * 64 + Mn * KVn * 64;
    rope_kernel<<<cdiv(nrope, TPB), TPB>>>(fcos, fsin);

    // Flash attention
    cudaFuncSetAttribute(attn_kernel, cudaFuncAttributeMaxDynamicSharedMemorySize,
                         ATTN_SMEM);
    attn_kernel<<<dim3(Sn / 64, Hn, Bn), TPB, ATTN_SMEM>>>();

    // O projection: expand attn output (reuse a3), GEMM into d_out
    expand3_kernel<<<cdiv(Mn * Dn, TPB), TPB>>>(attn_p, a3, Mn * Dn, 1);
    gemm_bf16_kernel<<<dim3(Dn / 128, Mn / 128), TPB>>>(a3, wo3, nullptr, out, Dn, K3n);
}

// round 5
// speedup vs baseline: 1.1275x; 1.1275x over previous
// R4: resubmit of R3 (never executed — broker infra failure). Fused fp32->bf16-split3
// conversion inside pipelined mma GEMM; attention/RoPE unchanged from verified R2.
// Label: "gemm-fused-split3-pipelined-retry".
#include <cuda_runtime.h>
#include <cuda_bf16.h>
#include <cstdint>

// Problem constants (Qwen2 GQA): B=2, S=2048, D=3584, H=28, KV=4, HD=128
#define Bn    2
#define Sn    2048
#define Dn    3584
#define Hn    28
#define KVn   4
#define HDn   128
#define NREP  7
#define Mn    (Bn * Sn)          // 4096 rows
#define KVD   (KVn * HDn)        // 512
#define SCALE 0.08838834764831845f

// fp32 scratch
__device__ float g_q[(size_t)Mn * Dn];
__device__ float g_k[(size_t)Mn * KVD];
__device__ float g_v[(size_t)Mn * KVD];
__device__ float g_attn[(size_t)Mn * Dn];

// ---------------------------------------------------------------------------
// Fused bf16-split3 tensor-core GEMM:
//   C[M,N] = A[M,K]*W[N,K]^T (+bias), A,W fp32 in global, fp32 accum/out.
// Each fp32 element k expands in-register to a bf16 triplet occupying smem
// K-positions 3k..3k+2:  A -> (hi,hi,lo),  W -> (hi,lo,hi), so a plain bf16
// dot over the expanded K gives hiA*hiW + hiA*loW + loA*hiW  (err ~2^-18).
// Block tile 128x128, fp32 K-step 16 (=48 bf16 = 3 mma k-steps), 256 threads
// = 8 warps (4 M x 2 N), warp tile 32x64, mma.sync m16n8k16 + ldmatrix.
// Register-prefetch pipeline: next tile's global loads issued before mma.
// ---------------------------------------------------------------------------
#define LDA 56   // bf16 row stride: 48 data + 8 pad (112B rows, LDSM conflict-free)

__device__ __forceinline__ void ldsm4(uint32_t& r0, uint32_t& r1,
                                      uint32_t& r2, uint32_t& r3, uint32_t addr)
{
    asm volatile("ldmatrix.sync.aligned.m8n8.x4.shared.b16 {%0,%1,%2,%3}, [%4];\n"
                 : "=r"(r0), "=r"(r1), "=r"(r2), "=r"(r3) : "r"(addr));
}

__device__ __forceinline__ void mma16816(float* c, const uint32_t* a,
                                         uint32_t b0, uint32_t b1)
{
    asm volatile(
        "mma.sync.aligned.m16n8k16.row.col.f32.bf16.bf16.f32 "
        "{%0,%1,%2,%3}, {%4,%5,%6,%7}, {%8,%9}, {%0,%1,%2,%3};\n"
        : "+f"(c[0]), "+f"(c[1]), "+f"(c[2]), "+f"(c[3])
        : "r"(a[0]), "r"(a[1]), "r"(a[2]), "r"(a[3]), "r"(b0), "r"(b1));
}

// Convert 8 fp32 -> 24 bf16 triplets and store (48 bytes as six 8B chunks).
// AMODE=1: (hi,hi,lo); AMODE=0: (hi,lo,hi).
template <int AMODE>
__device__ __forceinline__ void cvt_store24(__nv_bfloat16* dst, float4 v0, float4 v1)
{
    float f[8] = {v0.x, v0.y, v0.z, v0.w, v1.x, v1.y, v1.z, v1.w};
    __nv_bfloat16 t[24];
#pragma unroll
    for (int i = 0; i < 8; ++i) {
        __nv_bfloat16 hi = __float2bfloat16(f[i]);
        __nv_bfloat16 lo = __float2bfloat16(f[i] - __bfloat162float(hi));
        if (AMODE) { t[3*i] = hi; t[3*i+1] = hi; t[3*i+2] = lo; }
        else       { t[3*i] = hi; t[3*i+1] = lo; t[3*i+2] = hi; }
    }
    uint2*       d = (uint2*)dst;
    const uint2* s = (const uint2*)t;
#pragma unroll
    for (int j = 0; j < 6; ++j) d[j] = s[j];
}

__global__ void __launch_bounds__(256) gemm_f32tc_kernel(
    const float* __restrict__ A, const float* __restrict__ W,
    const float* __restrict__ bias, float* __restrict__ C, int N, int K)
{
    __shared__ __align__(16) __nv_bfloat16 As[128 * LDA];
    __shared__ __align__(16) __nv_bfloat16 Ws[128 * LDA];

    const int tid  = threadIdx.x;
    const int lane = tid & 31, wid = tid >> 5;
    const int m0 = blockIdx.y << 7, n0 = blockIdx.x << 7;
    const int wm = (wid & 3) << 5;        // warp M offset: 0/32/64/96
    const int wn = (wid >> 2) << 6;       // warp N offset: 0/64

    // producer mapping: thread -> (row 0..127, fp32 col offset 0 or 8)
    const int pr = tid >> 1;              // row
    const int pc = (tid & 1) << 3;        // fp32 col: 0 or 8
    const float* Ag = A + (size_t)(m0 + pr) * K + pc;
    const float* Wg = W + (size_t)(n0 + pr) * K + pc;
    __nv_bfloat16* Asd = &As[pr * LDA + pc * 3];
    __nv_bfloat16* Wsd = &Ws[pr * LDA + pc * 3];

    // ldmatrix lane->address components (same mapping as validated R2 kernel)
    const int a_row  = wm + (lane & 15);
    const int a_coff = (lane >> 4) << 3;
    const int b_row  = wn + ((lane >> 4) << 3) + (lane & 7);
    const int b_coff = ((lane >> 3) & 1) << 3;
    const uint32_t as_base = (uint32_t)__cvta_generic_to_shared(As);
    const uint32_t ws_base = (uint32_t)__cvta_generic_to_shared(Ws);

    float acc[2][8][4];
#pragma unroll
    for (int i = 0; i < 2; ++i)
#pragma unroll
        for (int j = 0; j < 8; ++j)
#pragma unroll
            for (int e = 0; e < 4; ++e) acc[i][j][e] = 0.f;

    // prefetch first tile into registers
    float4 pa0 = *(const float4*)(Ag);
    float4 pa1 = *(const float4*)(Ag + 4);
    float4 pw0 = *(const float4*)(Wg);
    float4 pw1 = *(const float4*)(Wg + 4);

    for (int k0 = 0; k0 < K; k0 += 16) {
        __syncthreads();                       // previous iter's readers done
        cvt_store24<1>(Asd, pa0, pa1);
        cvt_store24<0>(Wsd, pw0, pw1);
        __syncthreads();

        if (k0 + 16 < K) {                     // prefetch next tile (overlaps mma)
            pa0 = *(const float4*)(Ag + k0 + 16);
            pa1 = *(const float4*)(Ag + k0 + 20);
            pw0 = *(const float4*)(Wg + k0 + 16);
            pw1 = *(const float4*)(Wg + k0 + 20);
        }

#pragma unroll
        for (int ks = 0; ks < 3; ++ks) {
            const int kk = ks << 4;
            uint32_t afr[2][4];
#pragma unroll
            for (int mi = 0; mi < 2; ++mi) {
                uint32_t addr = as_base +
                    (uint32_t)(((a_row + mi * 16) * LDA + kk + a_coff) * 2);
                ldsm4(afr[mi][0], afr[mi][1], afr[mi][2], afr[mi][3], addr);
            }
            uint32_t bfr[4][4];
#pragma unroll
            for (int nq = 0; nq < 4; ++nq) {
                uint32_t addr = ws_base +
                    (uint32_t)(((b_row + nq * 16) * LDA + kk + b_coff) * 2);
                ldsm4(bfr[nq][0], bfr[nq][1], bfr[nq][2], bfr[nq][3], addr);
            }
#pragma unroll
            for (int mi = 0; mi < 2; ++mi)
#pragma unroll
                for (int nq = 0; nq < 4; ++nq) {
                    mma16816(acc[mi][nq * 2 + 0], afr[mi], bfr[nq][0], bfr[nq][1]);
                    mma16816(acc[mi][nq * 2 + 1], afr[mi], bfr[nq][2], bfr[nq][3]);
                }
        }
    }

    // Epilogue (same as R2): c0,c1 at (g, t*2|+1), c2,c3 at (g+8, ...)
    const int g = lane >> 2, t = lane & 3;
#pragma unroll
    for (int mi = 0; mi < 2; ++mi)
#pragma unroll
        for (int ni = 0; ni < 8; ++ni) {
            int row = m0 + wm + mi * 16 + g;
            int col = n0 + wn + ni * 8 + t * 2;
            float b0 = bias ? bias[col]     : 0.f;
            float b1 = bias ? bias[col + 1] : 0.f;
            C[(size_t)row * N + col]           = acc[mi][ni][0] + b0;
            C[(size_t)row * N + col + 1]       = acc[mi][ni][1] + b1;
            C[(size_t)(row + 8) * N + col]     = acc[mi][ni][2] + b0;
            C[(size_t)(row + 8) * N + col + 1] = acc[mi][ni][3] + b1;
        }
}

// ---------------------------------------------------------------------------
// RoPE, in place on g_q / g_k (unchanged).
// ---------------------------------------------------------------------------
__global__ void rope_kernel(const float* __restrict__ cosT,
                            const float* __restrict__ sinT)
{
    const int QP = Mn * Hn * 64;
    const int TP = QP + Mn * KVn * 64;
    int idx = blockIdx.x * blockDim.x + threadIdx.x;
    if (idx >= TP) return;

    float* ptr;
    int s, p;
    if (idx < QP) {
        p = idx & 63;
        int hh = (idx >> 6) % Hn;
        int bs = idx / (64 * Hn);
        s = bs & (Sn - 1);
        ptr = g_q + (size_t)bs * Dn + hh * HDn + 2 * p;
    } else {
        int t = idx - QP;
        p = t & 63;
        int kv = (t >> 6) & 3;
        int bs = t >> 8;
        s = bs & (Sn - 1);
        ptr = g_k + (size_t)bs * KVD + kv * HDn + 2 * p;
    }
    float c  = cosT[s * 64 + p];
    float sn = sinT[s * 64 + p];
    float xr = ptr[0], xi = ptr[1];
    ptr[0] = xr * c - xi * sn;
    ptr[1] = xr * sn + xi * c;
}

// ---------------------------------------------------------------------------
// fp32 flash attention, causal, GQA (unchanged from R2).
// ---------------------------------------------------------------------------
#define LQ 132
#define LP 68
#define ATTN_SMEM ((64 * LQ * 2 + 64 * 128 + 64 * LP) * 4)   // 117760 bytes

__global__ void __launch_bounds__(256) attn_kernel()
{
    extern __shared__ float sm[];
    float* Qs = sm;
    float* Ks = Qs + 64 * LQ;
    float* Vs = Ks + 64 * LQ;
    float* Ps = Vs + 64 * 128;

    const int qt = blockIdx.x, h = blockIdx.y, b = blockIdx.z;
    const int kvh = h / NREP;
    const int tid = threadIdx.x;
    const int tx = tid & 15, ty = tid >> 4;
    const int qi0 = qt << 6;

    const float* qbase = g_q + (size_t)(b * Sn + qi0) * Dn + h * HDn;
    for (int i = tid; i < 64 * 32; i += 256) {
        int r = i >> 5, c4 = (i & 31) << 2;
        *(float4*)(Qs + r * LQ + c4) = *(const float4*)(qbase + (size_t)r * Dn + c4);
    }

    float m[4], l[4], o[4][8];
#pragma unroll
    for (int i = 0; i < 4; ++i) {
        m[i] = -1e30f; l[i] = 0.f;
#pragma unroll
        for (int d = 0; d < 8; ++d) o[i][d] = 0.f;
    }

    const float* kb_g = g_k + (size_t)(b * Sn) * KVD + kvh * HDn;
    const float* vb_g = g_v + (size_t)(b * Sn) * KVD + kvh * HDn;

    for (int j0 = 0; j0 <= qi0; j0 += 64) {
        __syncthreads();
        for (int i = tid; i < 64 * 32; i += 256) {
            int r = i >> 5, c4 = (i & 31) << 2;
            *(float4*)(Ks + r * LQ  + c4) = *(const float4*)(kb_g + (size_t)(j0 + r) * KVD + c4);
            *(float4*)(Vs + r * 128 + c4) = *(const float4*)(vb_g + (size_t)(j0 + r) * KVD + c4);
        }
        __syncthreads();

        float sacc[4][4];
#pragma unroll
        for (int i = 0; i < 4; ++i)
#pragma unroll
            for (int j = 0; j < 4; ++j) sacc[i][j] = 0.f;

        for (int k = 0; k < 128; k += 4) {
            float4 qa[4], kb[4];
#pragma unroll
            for (int i = 0; i < 4; ++i)
                qa[i] = *(const float4*)(Qs + (ty * 4 + i) * LQ + k);
#pragma unroll
            for (int j = 0; j < 4; ++j)
                kb[j] = *(const float4*)(Ks + (tx * 4 + j) * LQ + k);
#pragma unroll
            for (int i = 0; i < 4; ++i)
#pragma unroll
                for (int j = 0; j < 4; ++j)
                    sacc[i][j] += qa[i].x * kb[j].x + qa[i].y * kb[j].y
                                + qa[i].z * kb[j].z + qa[i].w * kb[j].w;
        }

        const bool diag = (j0 == qi0);
#pragma unroll
        for (int i = 0; i < 4; ++i)
#pragma unroll
            for (int j = 0; j < 4; ++j) {
                float s = sacc[i][j] * SCALE;
                if (diag && (tx * 4 + j > ty * 4 + i)) s = -1e30f;
                sacc[i][j] = s;
            }

#pragma unroll
        for (int i = 0; i < 4; ++i) {
            float rm = sacc[i][0];
#pragma unroll
            for (int j = 1; j < 4; ++j) rm = fmaxf(rm, sacc[i][j]);
#pragma unroll
            for (int off = 8; off > 0; off >>= 1)
                rm = fmaxf(rm, __shfl_xor_sync(0xffffffffu, rm, off));
            float mn = fmaxf(m[i], rm);
            float alpha = __expf(m[i] - mn);
            float rs = 0.f;
#pragma unroll
            for (int j = 0; j < 4; ++j) {
                float p = __expf(sacc[i][j] - mn);
                sacc[i][j] = p;
                rs += p;
            }
#pragma unroll
            for (int off = 8; off > 0; off >>= 1)
                rs += __shfl_xor_sync(0xffffffffu, rs, off);
            l[i] = l[i] * alpha + rs;
            m[i] = mn;
#pragma unroll
            for (int d = 0; d < 8; ++d) o[i][d] *= alpha;
#pragma unroll
            for (int j = 0; j < 4; ++j)
                Ps[(ty * 4 + i) * LP + tx * 4 + j] = sacc[i][j];
        }
        __syncthreads();

        for (int j = 0; j < 64; ++j) {
            float4 v0 = *(const float4*)(Vs + j * 128 + tx * 8);
            float4 v1 = *(const float4*)(Vs + j * 128 + tx * 8 + 4);
#pragma unroll
            for (int i = 0; i < 4; ++i) {
                float p = Ps[(ty * 4 + i) * LP + j];
                o[i][0] += p * v0.x; o[i][1] += p * v0.y;
                o[i][2] += p * v0.z; o[i][3] += p * v0.w;
                o[i][4] += p * v1.x; o[i][5] += p * v1.y;
                o[i][6] += p * v1.z; o[i][7] += p * v1.w;
            }
        }
    }

    float* ob = g_attn + (size_t)(b * Sn + qi0) * Dn + h * HDn + tx * 8;
#pragma unroll
    for (int i = 0; i < 4; ++i) {
        float inv = 1.f / l[i];
        float outv[8];
#pragma unroll
        for (int d = 0; d < 8; ++d) outv[d] = o[i][d] * inv;
        float* p = ob + (size_t)(ty * 4 + i) * Dn;
        *(float4*)(p)     = *(float4*)(outv);
        *(float4*)(p + 4) = *(float4*)(outv + 4);
    }
}

// ---------------------------------------------------------------------------
// Launch. Inputs: x, wq_w, wq_b, wk_w, wk_b, wv_w, wv_b, wo_w, k_cache,
// v_cache, freqs_cos, freqs_sin, mask, start_pos. start_pos==0 -> caches/mask unused.
// ---------------------------------------------------------------------------
extern "C" void kernel_launch(void* const* d_in, const int* in_sizes, int n_in,
                              void* d_out, int out_size)
{
    const float* x    = (const float*)d_in[0];
    const float* wq_w = (const float*)d_in[1];
    const float* wq_b = (const float*)d_in[2];
    const float* wk_w = (const float*)d_in[3];
    const float* wk_b = (const float*)d_in[4];
    const float* wv_w = (const float*)d_in[5];
    const float* wv_b = (const float*)d_in[6];
    const float* wo_w = (const float*)d_in[7];
    const float* fcos = (const float*)d_in[10];
    const float* fsin = (const float*)d_in[11];
    float* out = (float*)d_out;

    float *q_p, *k_p, *v_p, *attn_p;
    cudaGetSymbolAddress((void**)&q_p,    g_q);
    cudaGetSymbolAddress((void**)&k_p,    g_k);
    cudaGetSymbolAddress((void**)&v_p,    g_v);
    cudaGetSymbolAddress((void**)&attn_p, g_attn);

    const int TPB = 256;
    auto cdiv = [](int a, int b) { return (a + b - 1) / b; };

    // QKV projections (fused convert + tensor cores)
    gemm_f32tc_kernel<<<dim3(Dn / 128,  Mn / 128), TPB>>>(x, wq_w, wq_b, q_p, Dn,  Dn);
    gemm_f32tc_kernel<<<dim3(KVD / 128, Mn / 128), TPB>>>(x, wk_w, wk_b, k_p, KVD, Dn);
    gemm_f32tc_kernel<<<dim3(KVD / 128, Mn / 128), TPB>>>(x, wv_w, wv_b, v_p, KVD, Dn);

    // RoPE
    int nrope = Mn * Hn * 64 + Mn * KVn * 64;
    rope_kernel<<<cdiv(nrope, TPB), TPB>>>(fcos, fsin);

    // Flash attention
    cudaFuncSetAttribute(attn_kernel, cudaFuncAttributeMaxDynamicSharedMemorySize,
                         ATTN_SMEM);
    attn_kernel<<<dim3(Sn / 64, Hn, Bn), TPB, ATTN_SMEM>>>();

    // O projection straight into d_out
    gemm_f32tc_kernel<<<dim3(Dn / 128, Mn / 128), TPB>>>(attn_p, wo_w, nullptr, out, Dn, Dn);
}

// round 6
// speedup vs baseline: 1.7607x; 1.5615x over previous
// R5: tensor-core flash attention (3-pass bf16 hi/lo mma, q-tile 128, ldmatrix.trans V).
// GEMM/RoPE unchanged from R4 (verified, 6692us). Label: "attn-mma-split3".
#include <cuda_runtime.h>
#include <cuda_bf16.h>
#include <cstdint>

// Problem constants (Qwen2 GQA): B=2, S=2048, D=3584, H=28, KV=4, HD=128
#define Bn    2
#define Sn    2048
#define Dn    3584
#define Hn    28
#define KVn   4
#define HDn   128
#define NREP  7
#define Mn    (Bn * Sn)          // 4096 rows
#define KVD   (KVn * HDn)        // 512
#define SCALE 0.08838834764831845f

// fp32 scratch
__device__ float g_q[(size_t)Mn * Dn];
__device__ float g_k[(size_t)Mn * KVD];
__device__ float g_v[(size_t)Mn * KVD];
__device__ float g_attn[(size_t)Mn * Dn];

// ===========================================================================
// Shared mma/ldsm helpers
// ===========================================================================
__device__ __forceinline__ void ldsm4(uint32_t& r0, uint32_t& r1,
                                      uint32_t& r2, uint32_t& r3, uint32_t addr)
{
    asm volatile("ldmatrix.sync.aligned.m8n8.x4.shared.b16 {%0,%1,%2,%3}, [%4];\n"
                 : "=r"(r0), "=r"(r1), "=r"(r2), "=r"(r3) : "r"(addr));
}

__device__ __forceinline__ void ldsm4t(uint32_t& r0, uint32_t& r1,
                                       uint32_t& r2, uint32_t& r3, uint32_t addr)
{
    asm volatile("ldmatrix.sync.aligned.m8n8.x4.trans.shared.b16 {%0,%1,%2,%3}, [%4];\n"
                 : "=r"(r0), "=r"(r1), "=r"(r2), "=r"(r3) : "r"(addr));
}

__device__ __forceinline__ void mma16816(float* c, const uint32_t* a,
                                         uint32_t b0, uint32_t b1)
{
    asm volatile(
        "mma.sync.aligned.m16n8k16.row.col.f32.bf16.bf16.f32 "
        "{%0,%1,%2,%3}, {%4,%5,%6,%7}, {%8,%9}, {%0,%1,%2,%3};\n"
        : "+f"(c[0]), "+f"(c[1]), "+f"(c[2]), "+f"(c[3])
        : "r"(a[0]), "r"(a[1]), "r"(a[2]), "r"(a[3]), "r"(b0), "r"(b1));
}

// ===========================================================================
// Fused bf16-split3 tensor-core GEMM (unchanged from R4, verified)
// ===========================================================================
#define LDA 56

template <int AMODE>
__device__ __forceinline__ void cvt_store24(__nv_bfloat16* dst, float4 v0, float4 v1)
{
    float f[8] = {v0.x, v0.y, v0.z, v0.w, v1.x, v1.y, v1.z, v1.w};
    __nv_bfloat16 t[24];
#pragma unroll
    for (int i = 0; i < 8; ++i) {
        __nv_bfloat16 hi = __float2bfloat16(f[i]);
        __nv_bfloat16 lo = __float2bfloat16(f[i] - __bfloat162float(hi));
        if (AMODE) { t[3*i] = hi; t[3*i+1] = hi; t[3*i+2] = lo; }
        else       { t[3*i] = hi; t[3*i+1] = lo; t[3*i+2] = hi; }
    }
    uint2*       d = (uint2*)dst;
    const uint2* s = (const uint2*)t;
#pragma unroll
    for (int j = 0; j < 6; ++j) d[j] = s[j];
}

__global__ void __launch_bounds__(256) gemm_f32tc_kernel(
    const float* __restrict__ A, const float* __restrict__ W,
    const float* __restrict__ bias, float* __restrict__ C, int N, int K)
{
    __shared__ __align__(16) __nv_bfloat16 As[128 * LDA];
    __shared__ __align__(16) __nv_bfloat16 Ws[128 * LDA];

    const int tid  = threadIdx.x;
    const int lane = tid & 31, wid = tid >> 5;
    const int m0 = blockIdx.y << 7, n0 = blockIdx.x << 7;
    const int wm = (wid & 3) << 5;
    const int wn = (wid >> 2) << 6;

    const int pr = tid >> 1;
    const int pc = (tid & 1) << 3;
    const float* Ag = A + (size_t)(m0 + pr) * K + pc;
    const float* Wg = W + (size_t)(n0 + pr) * K + pc;
    __nv_bfloat16* Asd = &As[pr * LDA + pc * 3];
    __nv_bfloat16* Wsd = &Ws[pr * LDA + pc * 3];

    const int a_row  = wm + (lane & 15);
    const int a_coff = (lane >> 4) << 3;
    const int b_row  = wn + ((lane >> 4) << 3) + (lane & 7);
    const int b_coff = ((lane >> 3) & 1) << 3;
    const uint32_t as_base = (uint32_t)__cvta_generic_to_shared(As);
    const uint32_t ws_base = (uint32_t)__cvta_generic_to_shared(Ws);

    float acc[2][8][4];
#pragma unroll
    for (int i = 0; i < 2; ++i)
#pragma unroll
        for (int j = 0; j < 8; ++j)
#pragma unroll
            for (int e = 0; e < 4; ++e) acc[i][j][e] = 0.f;

    float4 pa0 = *(const float4*)(Ag);
    float4 pa1 = *(const float4*)(Ag + 4);
    float4 pw0 = *(const float4*)(Wg);
    float4 pw1 = *(const float4*)(Wg + 4);

    for (int k0 = 0; k0 < K; k0 += 16) {
        __syncthreads();
        cvt_store24<1>(Asd, pa0, pa1);
        cvt_store24<0>(Wsd, pw0, pw1);
        __syncthreads();

        if (k0 + 16 < K) {
            pa0 = *(const float4*)(Ag + k0 + 16);
            pa1 = *(const float4*)(Ag + k0 + 20);
            pw0 = *(const float4*)(Wg + k0 + 16);
            pw1 = *(const float4*)(Wg + k0 + 20);
        }

#pragma unroll
        for (int ks = 0; ks < 3; ++ks) {
            const int kk = ks << 4;
            uint32_t afr[2][4];
#pragma unroll
            for (int mi = 0; mi < 2; ++mi) {
                uint32_t addr = as_base +
                    (uint32_t)(((a_row + mi * 16) * LDA + kk + a_coff) * 2);
                ldsm4(afr[mi][0], afr[mi][1], afr[mi][2], afr[mi][3], addr);
            }
            uint32_t bfr[4][4];
#pragma unroll
            for (int nq = 0; nq < 4; ++nq) {
                uint32_t addr = ws_base +
                    (uint32_t)(((b_row + nq * 16) * LDA + kk + b_coff) * 2);
                ldsm4(bfr[nq][0], bfr[nq][1], bfr[nq][2], bfr[nq][3], addr);
            }
#pragma unroll
            for (int mi = 0; mi < 2; ++mi)
#pragma unroll
                for (int nq = 0; nq < 4; ++nq) {
                    mma16816(acc[mi][nq * 2 + 0], afr[mi], bfr[nq][0], bfr[nq][1]);
                    mma16816(acc[mi][nq * 2 + 1], afr[mi], bfr[nq][2], bfr[nq][3]);
                }
        }
    }

    const int g = lane >> 2, t = lane & 3;
#pragma unroll
    for (int mi = 0; mi < 2; ++mi)
#pragma unroll
        for (int ni = 0; ni < 8; ++ni) {
            int row = m0 + wm + mi * 16 + g;
            int col = n0 + wn + ni * 8 + t * 2;
            float b0 = bias ? bias[col]     : 0.f;
            float b1 = bias ? bias[col + 1] : 0.f;
            C[(size_t)row * N + col]           = acc[mi][ni][0] + b0;
            C[(size_t)row * N + col + 1]       = acc[mi][ni][1] + b1;
            C[(size_t)(row + 8) * N + col]     = acc[mi][ni][2] + b0;
            C[(size_t)(row + 8) * N + col + 1] = acc[mi][ni][3] + b1;
        }
}

// ===========================================================================
// RoPE (unchanged)
// ===========================================================================
__global__ void rope_kernel(const float* __restrict__ cosT,
                            const float* __restrict__ sinT)
{
    const int QP = Mn * Hn * 64;
    const int TP = QP + Mn * KVn * 64;
    int idx = blockIdx.x * blockDim.x + threadIdx.x;
    if (idx >= TP) return;

    float* ptr;
    int s, p;
    if (idx < QP) {
        p = idx & 63;
        int hh = (idx >> 6) % Hn;
        int bs = idx / (64 * Hn);
        s = bs & (Sn - 1);
        ptr = g_q + (size_t)bs * Dn + hh * HDn + 2 * p;
    } else {
        int t = idx - QP;
        p = t & 63;
        int kv = (t >> 6) & 3;
        int bs = t >> 8;
        s = bs & (Sn - 1);
        ptr = g_k + (size_t)bs * KVD + kv * HDn + 2 * p;
    }
    float c  = cosT[s * 64 + p];
    float sn = sinT[s * 64 + p];
    float xr = ptr[0], xi = ptr[1];
    ptr[0] = xr * c - xi * sn;
    ptr[1] = xr * sn + xi * c;
}

// ===========================================================================
// Tensor-core flash attention, causal, GQA.
// Block: q-tile 128 rows x (head, batch). 256 threads = 8 warps x 16 rows.
// 3-pass hi/lo mma for S = Q K^T (K-dim 128) and O += P V (t-dim 64).
// V consumed via ldmatrix.trans from row-major (t, hd) smem: no transpose.
// ===========================================================================
#define LQA 136   // Q/K/V smem row stride (bf16): 272B, LDSM conflict-free
#define LPV 72    // P smem row stride (bf16): 144B
#define ATTN_SMEM ((2 * 128 * LQA + 4 * 64 * LQA + 2 * 128 * LPV) * 2)  // 176128 B

// convert 4 fp32 -> hi/lo bf16 pairs
__device__ __forceinline__ void cvt4hl(__nv_bfloat16* dhi, __nv_bfloat16* dlo, float4 v)
{
    float f[4] = {v.x, v.y, v.z, v.w};
    __nv_bfloat16 h[4], l[4];
#pragma unroll
    for (int i = 0; i < 4; ++i) {
        h[i] = __float2bfloat16(f[i]);
        l[i] = __float2bfloat16(f[i] - __bfloat162float(h[i]));
    }
    *(uint2*)dhi = *(const uint2*)h;
    *(uint2*)dlo = *(const uint2*)l;
}

__global__ void __launch_bounds__(256) attn_tc_kernel()
{
    extern __shared__ __align__(16) __nv_bfloat16 smb[];
    __nv_bfloat16* Qhi = smb;
    __nv_bfloat16* Qlo = Qhi + 128 * LQA;
    __nv_bfloat16* Khi = Qlo + 128 * LQA;
    __nv_bfloat16* Klo = Khi + 64 * LQA;
    __nv_bfloat16* Vhi = Klo + 64 * LQA;
    __nv_bfloat16* Vlo = Vhi + 64 * LQA;
    __nv_bfloat16* Phi = Vlo + 64 * LQA;
    __nv_bfloat16* Plo = Phi + 128 * LPV;

    const int qt = blockIdx.x, h = blockIdx.y, b = blockIdx.z;
    const int kvh = h / NREP;
    const int tid = threadIdx.x;
    const int lane = tid & 31, w = tid >> 5;
    const int qi0 = qt << 7;

    // --- convert Q tile (128x128 fp32 -> hi/lo bf16), once per block ---
    {
        const float* qg = g_q + (size_t)(b * Sn + qi0) * Dn + h * HDn;
        int r = tid >> 1, c0 = (tid & 1) << 6;
#pragma unroll
        for (int c = 0; c < 64; c += 4) {
            float4 v = *(const float4*)(qg + (size_t)r * Dn + c0 + c);
            cvt4hl(Qhi + r * LQA + c0 + c, Qlo + r * LQA + c0 + c, v);
        }
    }

    // fragment address components (validated mappings)
    const int a_row_l = lane & 15;
    const int a_coff  = (lane >> 4) << 3;
    const int b_row_l = ((lane >> 4) << 3) + (lane & 7);
    const int b_coff  = ((lane >> 3) & 1) << 3;
    // trans (V) mapping: row within k16, col within 16-wide hd group
    const int t_row = (((lane >> 3) & 1) << 3) + (lane & 7);
    const int t_col = (lane >> 4) << 3;

    const uint32_t qhi_b = (uint32_t)__cvta_generic_to_shared(Qhi);
    const uint32_t qlo_b = (uint32_t)__cvta_generic_to_shared(Qlo);
    const uint32_t khi_b = (uint32_t)__cvta_generic_to_shared(Khi);
    const uint32_t klo_b = (uint32_t)__cvta_generic_to_shared(Klo);
    const uint32_t vhi_b = (uint32_t)__cvta_generic_to_shared(Vhi);
    const uint32_t vlo_b = (uint32_t)__cvta_generic_to_shared(Vlo);
    const uint32_t phi_b = (uint32_t)__cvta_generic_to_shared(Phi);
    const uint32_t plo_b = (uint32_t)__cvta_generic_to_shared(Plo);

    const int g  = lane >> 2;        // c-layout row within 8
    const int t4 = lane & 3;         // c-layout col pair
    const int qglob0 = qi0 + w * 16 + g;   // this thread's rows
    const int qglob1 = qglob0 + 8;

    float oacc[16][4];
#pragma unroll
    for (int i = 0; i < 16; ++i)
#pragma unroll
        for (int e = 0; e < 4; ++e) oacc[i][e] = 0.f;
    float m0 = -1e30f, m1 = -1e30f, l0 = 0.f, l1 = 0.f;

    const float* kg_base = g_k + (size_t)(b * Sn) * KVD + kvh * HDn;
    const float* vg_base = g_v + (size_t)(b * Sn) * KVD + kvh * HDn;

    const int jmax = qi0 + 64;
    for (int j0 = 0; j0 <= jmax; j0 += 64) {
        // --- convert K, V tiles (64x128 each) ---
        __syncthreads();
        {
            int r = tid >> 2, c0 = (tid & 3) << 5;
            const float* kg = kg_base + (size_t)(j0 + r) * KVD + c0;
            const float* vg = vg_base + (size_t)(j0 + r) * KVD + c0;
#pragma unroll
            for (int c = 0; c < 32; c += 4) {
                cvt4hl(Khi + r * LQA + c0 + c, Klo + r * LQA + c0 + c,
                       *(const float4*)(kg + c));
                cvt4hl(Vhi + r * LQA + c0 + c, Vlo + r * LQA + c0 + c,
                       *(const float4*)(vg + c));
            }
        }
        __syncthreads();

        // --- S = Q K^T : 3 passes x 8 k-steps, warp tile 16x64 ---
        float sacc[8][4];
#pragma unroll
        for (int i = 0; i < 8; ++i)
#pragma unroll
            for (int e = 0; e < 4; ++e) sacc[i][e] = 0.f;

#pragma unroll
        for (int pass = 0; pass < 3; ++pass) {
            const uint32_t ab = (pass == 2) ? qlo_b : qhi_b;
            const uint32_t bb = (pass == 1) ? klo_b : khi_b;
#pragma unroll
            for (int ks = 0; ks < 8; ++ks) {
                const int kk = ks << 4;
                uint32_t afr[4];
                ldsm4(afr[0], afr[1], afr[2], afr[3],
                      ab + (uint32_t)(((w * 16 + a_row_l) * LQA + kk + a_coff) * 2));
                uint32_t bfr[4][4];
#pragma unroll
                for (int nq = 0; nq < 4; ++nq)
                    ldsm4(bfr[nq][0], bfr[nq][1], bfr[nq][2], bfr[nq][3],
                          bb + (uint32_t)(((nq * 16 + b_row_l) * LQA + kk + b_coff) * 2));
#pragma unroll
                for (int nq = 0; nq < 4; ++nq) {
                    mma16816(sacc[nq * 2 + 0], afr, bfr[nq][0], bfr[nq][1]);
                    mma16816(sacc[nq * 2 + 1], afr, bfr[nq][2], bfr[nq][3]);
                }
            }
        }

        // --- scale + causal mask ---
#pragma unroll
        for (int nq = 0; nq < 8; ++nq) {
            int cb = j0 + nq * 8 + t4 * 2;
            float s0 = sacc[nq][0] * SCALE;
            float s1 = sacc[nq][1] * SCALE;
            float s2 = sacc[nq][2] * SCALE;
            float s3 = sacc[nq][3] * SCALE;
            if (cb     > qglob0) s0 = -1e30f;
            if (cb + 1 > qglob0) s1 = -1e30f;
            if (cb     > qglob1) s2 = -1e30f;
            if (cb + 1 > qglob1) s3 = -1e30f;
            sacc[nq][0] = s0; sacc[nq][1] = s1;
            sacc[nq][2] = s2; sacc[nq][3] = s3;
        }

        // --- online softmax (rows g, g+8; quad shuffle reduce) ---
        float rm0 = -1e30f, rm1 = -1e30f;
#pragma unroll
        for (int nq = 0; nq < 8; ++nq) {
            rm0 = fmaxf(rm0, fmaxf(sacc[nq][0], sacc[nq][1]));
            rm1 = fmaxf(rm1, fmaxf(sacc[nq][2], sacc[nq][3]));
        }
        rm0 = fmaxf(rm0, __shfl_xor_sync(0xffffffffu, rm0, 1));
        rm0 = fmaxf(rm0, __shfl_xor_sync(0xffffffffu, rm0, 2));
        rm1 = fmaxf(rm1, __shfl_xor_sync(0xffffffffu, rm1, 1));
        rm1 = fmaxf(rm1, __shfl_xor_sync(0xffffffffu, rm1, 2));
        float mn0 = fmaxf(m0, rm0), mn1 = fmaxf(m1, rm1);
        float al0 = __expf(m0 - mn0), al1 = __expf(m1 - mn1);

        __syncwarp();   // prior PV reads of Phi/Plo done before overwrite
        float rs0 = 0.f, rs1 = 0.f;
        const int prow0 = w * 16 + g;
#pragma unroll
        for (int nq = 0; nq < 8; ++nq) {
            int col = nq * 8 + t4 * 2;
            float p0 = __expf(sacc[nq][0] - mn0);
            float p1 = __expf(sacc[nq][1] - mn0);
            float p2 = __expf(sacc[nq][2] - mn1);
            float p3 = __expf(sacc[nq][3] - mn1);
            rs0 += p0 + p1;  rs1 += p2 + p3;
            __nv_bfloat162 h01, l01, h23, l23;
            h01.x = __float2bfloat16(p0);
            h01.y = __float2bfloat16(p1);
            l01.x = __float2bfloat16(p0 - __bfloat162float(h01.x));
            l01.y = __float2bfloat16(p1 - __bfloat162float(h01.y));
            h23.x = __float2bfloat16(p2);
            h23.y = __float2bfloat16(p3);
            l23.x = __float2bfloat16(p2 - __bfloat162float(h23.x));
            l23.y = __float2bfloat16(p3 - __bfloat162float(h23.y));
            *(__nv_bfloat162*)(Phi + prow0 * LPV + col)       = h01;
            *(__nv_bfloat162*)(Plo + prow0 * LPV + col)       = l01;
            *(__nv_bfloat162*)(Phi + (prow0 + 8) * LPV + col) = h23;
            *(__nv_bfloat162*)(Plo + (prow0 + 8) * LPV + col) = l23;
        }
        rs0 += __shfl_xor_sync(0xffffffffu, rs0, 1);
        rs0 += __shfl_xor_sync(0xffffffffu, rs0, 2);
        rs1 += __shfl_xor_sync(0xffffffffu, rs1, 1);
        rs1 += __shfl_xor_sync(0xffffffffu, rs1, 2);
        l0 = l0 * al0 + rs0;  l1 = l1 * al1 + rs1;
        m0 = mn0;  m1 = mn1;
#pragma unroll
        for (int nn = 0; nn < 16; ++nn) {
            oacc[nn][0] *= al0; oacc[nn][1] *= al0;
            oacc[nn][2] *= al1; oacc[nn][3] *= al1;
        }
        __syncwarp();   // Phi/Plo writes visible to ldmatrix below

        // --- O += P V : 3 passes x 4 k-steps, warp tile 16x128 ---
#pragma unroll
        for (int pass = 0; pass < 3; ++pass) {
            const uint32_t ab = (pass == 2) ? plo_b : phi_b;
            const uint32_t bb = (pass == 1) ? vlo_b : vhi_b;
#pragma unroll
            for (int ks = 0; ks < 4; ++ks) {
                const int kk = ks << 4;
                uint32_t afr[4];
                ldsm4(afr[0], afr[1], afr[2], afr[3],
                      ab + (uint32_t)(((w * 16 + a_row_l) * LPV + kk + a_coff) * 2));
#pragma unroll
                for (int nh = 0; nh < 8; ++nh) {
                    uint32_t b0, b1, b2, b3;
                    ldsm4t(b0, b1, b2, b3,
                           bb + (uint32_t)(((kk + t_row) * LQA + nh * 16 + t_col) * 2));
                    mma16816(oacc[nh * 2 + 0], afr, b0, b1);
                    mma16816(oacc[nh * 2 + 1], afr, b2, b3);
                }
            }
        }
    }

    // --- epilogue: normalize, write g_attn ---
    float inv0 = 1.f / l0, inv1 = 1.f / l1;
    float* ob0 = g_attn + (size_t)(b * Sn + qglob0) * Dn + h * HDn;
    float* ob1 = g_attn + (size_t)(b * Sn + qglob1) * Dn + h * HDn;
#pragma unroll
    for (int nn = 0; nn < 16; ++nn) {
        int col = nn * 8 + t4 * 2;
        float2 v0 = {oacc[nn][0] * inv0, oacc[nn][1] * inv0};
        float2 v1 = {oacc[nn][2] * inv1, oacc[nn][3] * inv1};
        *(float2*)(ob0 + col) = v0;
        *(float2*)(ob1 + col) = v1;
    }
}

// ===========================================================================
// Launch
// ===========================================================================
extern "C" void kernel_launch(void* const* d_in, const int* in_sizes, int n_in,
                              void* d_out, int out_size)
{
    const float* x    = (const float*)d_in[0];
    const float* wq_w = (const float*)d_in[1];
    const float* wq_b = (const float*)d_in[2];
    const float* wk_w = (const float*)d_in[3];
    const float* wk_b = (const float*)d_in[4];
    const float* wv_w = (const float*)d_in[5];
    const float* wv_b = (const float*)d_in[6];
    const float* wo_w = (const float*)d_in[7];
    const float* fcos = (const float*)d_in[10];
    const float* fsin = (const float*)d_in[11];
    float* out = (float*)d_out;

    float *q_p, *k_p, *v_p, *attn_p;
    cudaGetSymbolAddress((void**)&q_p,    g_q);
    cudaGetSymbolAddress((void**)&k_p,    g_k);
    cudaGetSymbolAddress((void**)&v_p,    g_v);
    cudaGetSymbolAddress((void**)&attn_p, g_attn);

    const int TPB = 256;
    auto cdiv = [](int a, int b) { return (a + b - 1) / b; };

    gemm_f32tc_kernel<<<dim3(Dn / 128,  Mn / 128), TPB>>>(x, wq_w, wq_b, q_p, Dn,  Dn);
    gemm_f32tc_kernel<<<dim3(KVD / 128, Mn / 128), TPB>>>(x, wk_w, wk_b, k_p, KVD, Dn);
    gemm_f32tc_kernel<<<dim3(KVD / 128, Mn / 128), TPB>>>(x, wv_w, wv_b, v_p, KVD, Dn);

    int nrope = Mn * Hn * 64 + Mn * KVn * 64;
    rope_kernel<<<cdiv(nrope, TPB), TPB>>>(fcos, fsin);

    cudaFuncSetAttribute(attn_tc_kernel, cudaFuncAttributeMaxDynamicSharedMemorySize,
                         ATTN_SMEM);
    attn_tc_kernel<<<dim3(Sn / 128, Hn, Bn), TPB, ATTN_SMEM>>>();

    gemm_f32tc_kernel<<<dim3(Dn / 128, Mn / 128), TPB>>>(attn_p, wo_w, nullptr, out, Dn, Dn);
}